// round 1
// baseline (speedup 1.0000x reference)
#include <cuda_runtime.h>

// ---------------------------------------------------------------------------
// ConvDiffLogicMNIST — difflogic CNN forward.
// Core trick: each soft logic gate  out = sum_k softmax(w)_k * op_k(a,b)
// collapses to out = A + B*a + C*b + D*a*b with per-gate precomputed (A,B,C,D).
// ---------------------------------------------------------------------------

#define DEV_INLINE __device__ __forceinline__

static constexpr int B_MAX = 100;

// ---- coefficient table offsets (in float4 units) ----
static constexpr int OFF_C1_0 = 0;       // 16*4 = 64
static constexpr int OFF_C1_1 = 64;      // 16*2 = 32
static constexpr int OFF_C1_2 = 96;      // 16*1 = 16
static constexpr int OFF_C2_0 = 112;     // 48*4 = 192
static constexpr int OFF_C2_1 = 304;     // 48*2 = 96
static constexpr int OFF_C2_2 = 400;     // 48*1 = 48
static constexpr int OFF_C3_0 = 448;     // 144*4 = 576
static constexpr int OFF_C3_1 = 1024;    // 144*2 = 288
static constexpr int OFF_C3_2 = 1312;    // 144*1 = 144
static constexpr int OFF_FC1  = 1456;    // 20480
static constexpr int OFF_FC2  = 21936;   // 10240
static constexpr int OFF_FC3  = 32176;   // 5120
static constexpr int N_GATES  = 37296;

// ---- device scratch (no allocation allowed) ----
__device__ float4 g_coef[40960];
__device__ float  g_act1[B_MAX * 16 * 12 * 12];   // pooled conv1
__device__ float  g_act2[B_MAX * 48 * 6 * 6];     // pooled conv2
__device__ float  g_act3[B_MAX * 144 * 3 * 3];    // pooled conv3 (flatten order)
__device__ float  g_fc1[B_MAX * 20480];
__device__ float  g_fc2[B_MAX * 10240];
__device__ float  g_fc3[B_MAX * 5120];

// op -> (const, a, b, ab) coefficients for the 16 two-input soft boolean ops
__constant__ float OPC0[16]  = {0,0,0,0, 0,0,0,0, 1,1,1,1, 1,1,1,1};
__constant__ float OPCA[16]  = {0,0,1,1, 0,0,1,1, -1,-1,0,0, -1,-1,0,0};
__constant__ float OPCB[16]  = {0,0,0,0, 1,1,1,1, -1,-1,-1,-1, 0,0,0,0};
__constant__ float OPCAB[16] = {0,1,-1,0, -1,0,-2,-1, 1,2,0,1, 0,1,-1,0};

DEV_INLINE float gate_eval(float4 c, float a, float b) {
    // A + B*a + C*b + D*a*b
    return fmaf(b, fmaf(a, c.w, c.z), fmaf(a, c.y, c.x));
}

DEV_INLINE float sel4(const float h[4], int i) {
    float r = h[0];
    r = (i == 1) ? h[1] : r;
    r = (i == 2) ? h[2] : r;
    r = (i == 3) ? h[3] : r;
    return r;
}
DEV_INLINE float sel2(const float h[2], int i) {
    return (i == 1) ? h[1] : h[0];
}

// ---------------------------------------------------------------------------
// Kernel 1: softmax(w) -> (A,B,C,D) per gate, for all 12 weight arrays at once
// ---------------------------------------------------------------------------
struct CoefSeg { const float* w; int off; int cnt; };
struct CoefArgs { CoefSeg s[12]; };

__global__ void coef_kernel(CoefArgs args) {
    int tid = blockIdx.x * blockDim.x + threadIdx.x;
    if (tid >= N_GATES) return;
    int rem = tid, i = 0;
    while (rem >= args.s[i].cnt) { rem -= args.s[i].cnt; i++; }
    const float* w = args.s[i].w + rem * 16;

    float wv[16], m = -1e30f;
#pragma unroll
    for (int k = 0; k < 16; k++) { wv[k] = w[k]; m = fmaxf(m, wv[k]); }
    float e[16], sum = 0.f;
#pragma unroll
    for (int k = 0; k < 16; k++) { e[k] = expf(wv[k] - m); sum += e[k]; }
    float inv = 1.f / sum;
    float A = 0.f, Bc = 0.f, Cc = 0.f, D = 0.f;
#pragma unroll
    for (int k = 0; k < 16; k++) {
        float p = e[k] * inv;
        A  = fmaf(p, OPC0[k],  A);
        Bc = fmaf(p, OPCA[k],  Bc);
        Cc = fmaf(p, OPCB[k],  Cc);
        D  = fmaf(p, OPCAB[k], D);
    }
    g_coef[args.s[i].off + rem] = make_float4(A, Bc, Cc, D);
}

// ---------------------------------------------------------------------------
// Kernel 2: fused conv (logic-tree) + 2x2 max pool. One thread per pooled out.
// LAYER 0: in = x (binarize), out = g_act1
// LAYER 1: in = g_act1,       out = g_act2
// LAYER 2: in = g_act2,       out = g_act3
// ---------------------------------------------------------------------------
template <int CIN, int HIN, int KS, int PAD, int F, bool BIN, int OFF, int LAYER>
__global__ void conv_kernel(const float* __restrict__ xin,
                            const int* __restrict__ idx0,
                            const int* __restrict__ idx1,
                            const int* __restrict__ idx2,
                            int B) {
    constexpr int OH  = HIN + 2 * PAD - KS + 1;
    constexpr int OHP = OH / 2;
    const int total = B * F * OHP * OHP;
    int tid = blockIdx.x * blockDim.x + threadIdx.x;
    if (tid >= total) return;

    const float* in = (LAYER == 0) ? xin : (LAYER == 1) ? g_act1 : g_act2;
    float* out = (LAYER == 0) ? g_act1 : (LAYER == 1) ? g_act2 : g_act3;

    int px = tid % OHP;
    int py = (tid / OHP) % OHP;
    int f  = (tid / (OHP * OHP)) % F;
    int b  = tid / (OHP * OHP * F);

    // gate wiring for filter f
    int i0a[4], i0b[4];
#pragma unroll
    for (int g = 0; g < 4; g++) {
        i0a[g] = idx0[f * 4 + g];
        i0b[g] = idx0[F * 4 + f * 4 + g];
    }
    int i1a[2], i1b[2];
#pragma unroll
    for (int g = 0; g < 2; g++) {
        i1a[g] = idx1[f * 2 + g];
        i1b[g] = idx1[F * 2 + f * 2 + g];
    }
    int i2a = idx2[f], i2b = idx2[F + f];

    // decompose the 8 level-0 patch indices -> (channel, ky, kx)
    int pc[8], pky[8], pkx[8];
#pragma unroll
    for (int j = 0; j < 8; j++) {
        int p = (j < 4) ? i0a[j] : i0b[j - 4];
        pc[j] = p / (KS * KS);
        int kk = p % (KS * KS);
        pky[j] = kk / KS;
        pkx[j] = kk % KS;
    }

    float4 c0[4], c1[2], c2;
#pragma unroll
    for (int g = 0; g < 4; g++) c0[g] = g_coef[OFF + f * 4 + g];
#pragma unroll
    for (int g = 0; g < 2; g++) c1[g] = g_coef[OFF + F * 4 + f * 2 + g];
    c2 = g_coef[OFF + F * 6 + f];

    const float* inb = in + (long)b * CIN * HIN * HIN;
    float m = -1e30f;
#pragma unroll
    for (int dy = 0; dy < 2; dy++) {
#pragma unroll
        for (int dx = 0; dx < 2; dx++) {
            int y = 2 * py + dy, x = 2 * px + dx;
            float v[8];
#pragma unroll
            for (int j = 0; j < 8; j++) {
                int iy = y + pky[j] - PAD;
                int ix = x + pkx[j] - PAD;
                float t = 0.f;
                if (PAD == 0 ||
                    ((unsigned)iy < (unsigned)HIN && (unsigned)ix < (unsigned)HIN))
                    t = inb[(pc[j] * HIN + iy) * HIN + ix];
                if (BIN) t = (t > 0.5f) ? 1.f : 0.f;
                v[j] = t;
            }
            float h0[4];
#pragma unroll
            for (int g = 0; g < 4; g++) h0[g] = gate_eval(c0[g], v[g], v[g + 4]);
            float h1[2];
#pragma unroll
            for (int g = 0; g < 2; g++)
                h1[g] = gate_eval(c1[g], sel4(h0, i1a[g]), sel4(h0, i1b[g]));
            float o = gate_eval(c2, sel2(h1, i2a), sel2(h1, i2b));
            m = fmaxf(m, o);
        }
    }
    out[tid] = m;
}

// ---------------------------------------------------------------------------
// Kernel 3: FC logic layer. One thread per (b, o), b-major for L1 locality.
// ---------------------------------------------------------------------------
template <int LAYER>
__global__ void fc_kernel(const int* __restrict__ idx, int B) {
    constexpr int DIN  = (LAYER == 0) ? 1296 : (LAYER == 1) ? 20480 : 10240;
    constexpr int DOUT = (LAYER == 0) ? 20480 : (LAYER == 1) ? 10240 : 5120;
    constexpr int OFF  = (LAYER == 0) ? OFF_FC1 : (LAYER == 1) ? OFF_FC2 : OFF_FC3;

    const float* in = (LAYER == 0) ? g_act3 : (LAYER == 1) ? g_fc1 : g_fc2;
    float* out = (LAYER == 0) ? g_fc1 : (LAYER == 1) ? g_fc2 : g_fc3;

    int tid = blockIdx.x * blockDim.x + threadIdx.x;
    if (tid >= B * DOUT) return;
    int o = tid % DOUT;
    int b = tid / DOUT;

    float a  = in[b * DIN + idx[o]];
    float bb = in[b * DIN + idx[DOUT + o]];
    float4 c = g_coef[OFF + o];
    out[tid] = gate_eval(c, a, bb);
}

// ---------------------------------------------------------------------------
// Kernel 4: group-sum: [B, 10, 512] -> sum over 512, / 30. Block per (b,d).
// ---------------------------------------------------------------------------
__global__ void groupsum_kernel(float* __restrict__ out) {
    int bd = blockIdx.x;
    const float* p = g_fc3 + (long)bd * 512;
    float s = 0.f;
    for (int i = threadIdx.x; i < 512; i += blockDim.x) s += p[i];
#pragma unroll
    for (int o = 16; o; o >>= 1) s += __shfl_xor_sync(0xffffffffu, s, o);
    __shared__ float ws[8];
    int w = threadIdx.x >> 5, lane = threadIdx.x & 31;
    if (lane == 0) ws[w] = s;
    __syncthreads();
    if (threadIdx.x == 0) {
        float t = 0.f;
        int nw = blockDim.x >> 5;
        for (int i = 0; i < nw; i++) t += ws[i];
        out[bd] = t / 30.f;
    }
}

// ---------------------------------------------------------------------------
static inline int cdiv(int a, int b) { return (a + b - 1) / b; }

extern "C" void kernel_launch(void* const* d_in, const int* in_sizes, int n_in,
                              void* d_out, int out_size) {
    const float* x = (const float*)d_in[0];
    const int B = in_sizes[0] / (28 * 28);

    const int* c1_i0 = (const int*)d_in[1];
    const float* c1_w0 = (const float*)d_in[2];
    const int* c1_i1 = (const int*)d_in[3];
    const float* c1_w1 = (const float*)d_in[4];
    const int* c1_i2 = (const int*)d_in[5];
    const float* c1_w2 = (const float*)d_in[6];
    const int* c2_i0 = (const int*)d_in[7];
    const float* c2_w0 = (const float*)d_in[8];
    const int* c2_i1 = (const int*)d_in[9];
    const float* c2_w1 = (const float*)d_in[10];
    const int* c2_i2 = (const int*)d_in[11];
    const float* c2_w2 = (const float*)d_in[12];
    const int* c3_i0 = (const int*)d_in[13];
    const float* c3_w0 = (const float*)d_in[14];
    const int* c3_i1 = (const int*)d_in[15];
    const float* c3_w1 = (const float*)d_in[16];
    const int* c3_i2 = (const int*)d_in[17];
    const float* c3_w2 = (const float*)d_in[18];
    const int* fc1_i = (const int*)d_in[19];
    const float* fc1_w = (const float*)d_in[20];
    const int* fc2_i = (const int*)d_in[21];
    const float* fc2_w = (const float*)d_in[22];
    const int* fc3_i = (const int*)d_in[23];
    const float* fc3_w = (const float*)d_in[24];
    float* out = (float*)d_out;

    // 1) coefficients
    CoefArgs ca;
    ca.s[0]  = {c1_w0, OFF_C1_0, 64};
    ca.s[1]  = {c1_w1, OFF_C1_1, 32};
    ca.s[2]  = {c1_w2, OFF_C1_2, 16};
    ca.s[3]  = {c2_w0, OFF_C2_0, 192};
    ca.s[4]  = {c2_w1, OFF_C2_1, 96};
    ca.s[5]  = {c2_w2, OFF_C2_2, 48};
    ca.s[6]  = {c3_w0, OFF_C3_0, 576};
    ca.s[7]  = {c3_w1, OFF_C3_1, 288};
    ca.s[8]  = {c3_w2, OFF_C3_2, 144};
    ca.s[9]  = {fc1_w, OFF_FC1, 20480};
    ca.s[10] = {fc2_w, OFF_FC2, 10240};
    ca.s[11] = {fc3_w, OFF_FC3, 5120};
    coef_kernel<<<cdiv(N_GATES, 256), 256>>>(ca);

    // 2) conv stack (each fused with binarize/pool)
    conv_kernel<1, 28, 5, 0, 16, true, OFF_C1_0, 0>
        <<<cdiv(B * 16 * 12 * 12, 256), 256>>>(x, c1_i0, c1_i1, c1_i2, B);
    conv_kernel<16, 12, 3, 1, 48, false, OFF_C2_0, 1>
        <<<cdiv(B * 48 * 6 * 6, 256), 256>>>(x, c2_i0, c2_i1, c2_i2, B);
    conv_kernel<48, 6, 3, 1, 144, false, OFF_C3_0, 2>
        <<<cdiv(B * 144 * 3 * 3, 256), 256>>>(x, c3_i0, c3_i1, c3_i2, B);

    // 3) fc stack
    fc_kernel<0><<<cdiv(B * 20480, 256), 256>>>(fc1_i, B);
    fc_kernel<1><<<cdiv(B * 10240, 256), 256>>>(fc2_i, B);
    fc_kernel<2><<<cdiv(B * 5120, 256), 256>>>(fc3_i, B);

    // 4) group sum
    groupsum_kernel<<<B * 10, 128>>>(out);
}

// round 2
// speedup vs baseline: 1.3741x; 1.3741x over previous
#include <cuda_runtime.h>
#include <cuda_fp16.h>

// ---------------------------------------------------------------------------
// ConvDiffLogicMNIST — difflogic CNN forward, fully fused.
// Gate algebra: out = A + B*a + C*b + D*a*b (per-gate coefs from softmax(w)).
// Kernel 1: coef/pack prep.  Kernel 2: block-per-image mega kernel, whole net
// in shared memory (binarize -> conv1..3 (+pool) -> fc1..3 -> groupsum).
// ---------------------------------------------------------------------------

#define DEV_INLINE __device__ __forceinline__

static constexpr int NT = 512;   // threads per mega block

// ---- conv coefficient table offsets (float4 units) ----
static constexpr int OFF_C1_0 = 0;       // 16*4
static constexpr int OFF_C1_1 = 64;      // 16*2
static constexpr int OFF_C1_2 = 96;      // 16*1
static constexpr int OFF_C2_0 = 112;     // 48*4
static constexpr int OFF_C2_1 = 304;     // 48*2
static constexpr int OFF_C2_2 = 400;     // 48*1
static constexpr int OFF_C3_0 = 448;     // 144*4
static constexpr int OFF_C3_1 = 1024;    // 144*2
static constexpr int OFF_C3_2 = 1312;    // 144*1
static constexpr int N_CONV_COEF = 1456;

// ---- fc gate offsets (gate units) ----
static constexpr int FC1_OFF = 0;        // 20480
static constexpr int FC2_OFF = 20480;    // 10240
static constexpr int FC3_OFF = 30720;    // 5120
static constexpr int N_FC    = 35840;
static constexpr int N_GATES = 37296;    // conv gates (1456) + fc gates (35840)

// ---- smem layout (float units) ----
static constexpr int S_XBIN = 0;                  // 784
static constexpr int S_ACT1 = 784;                // 16*12*12 = 2304
static constexpr int S_ACT2 = S_ACT1 + 2304;      // 48*6*6  = 1728
static constexpr int S_ACT3 = S_ACT2 + 1728;      // 144*3*3 = 1296
static constexpr int S_FC1  = S_ACT3 + 1296;      // 20480  (reused for fc3 out)
static constexpr int S_FC2  = S_FC1 + 20480;      // 10240
static constexpr int S_WIRE = S_FC2 + 10240;      // 144*9 ints
static constexpr int SMEM_BYTES = (S_WIRE + 144 * 9) * 4;

// ---- device scratch ----
__device__ float4   g_coef[N_CONV_COEF];     // conv gate coefs (fp32)
__device__ unsigned g_fcidx[N_FC];           // packed (ia | ib<<16)
__device__ __half2  g_fch[N_FC * 2];         // fc coefs: (A,B),(C,D)

// op -> (const, a, b, ab) coefficients for the 16 two-input soft boolean ops
__constant__ float OPC0[16]  = {0,0,0,0, 0,0,0,0, 1,1,1,1, 1,1,1,1};
__constant__ float OPCA[16]  = {0,0,1,1, 0,0,1,1, -1,-1,0,0, -1,-1,0,0};
__constant__ float OPCB[16]  = {0,0,0,0, 1,1,1,1, -1,-1,-1,-1, 0,0,0,0};
__constant__ float OPCAB[16] = {0,1,-1,0, -1,0,-2,-1, 1,2,0,1, 0,1,-1,0};

DEV_INLINE float gate_eval(float A, float Bc, float Cc, float D, float a, float b) {
    return fmaf(b, fmaf(a, D, Cc), fmaf(a, Bc, A));
}
DEV_INLINE float gate_eval4(float4 c, float a, float b) {
    return gate_eval(c.x, c.y, c.z, c.w, a, b);
}
DEV_INLINE float sel4(const float h[4], int i) {
    float r = h[0];
    r = (i == 1) ? h[1] : r;
    r = (i == 2) ? h[2] : r;
    r = (i == 3) ? h[3] : r;
    return r;
}

// ---------------------------------------------------------------------------
// Kernel 1: softmax(w) -> (A,B,C,D); conv -> g_coef fp32; fc -> packed idx +
// half coefs.
// ---------------------------------------------------------------------------
struct CoefSeg { const float* w; const int* idx; int off; int cnt; };
struct CoefArgs { CoefSeg s[12]; };

__global__ void coef_kernel(CoefArgs args) {
    int tid = blockIdx.x * blockDim.x + threadIdx.x;
    if (tid >= N_GATES) return;
    int rem = tid, i = 0;
    while (rem >= args.s[i].cnt) { rem -= args.s[i].cnt; i++; }
    const float* w = args.s[i].w + rem * 16;

    float wv[16], m = -1e30f;
#pragma unroll
    for (int k = 0; k < 16; k++) { wv[k] = w[k]; m = fmaxf(m, wv[k]); }
    float e[16], sum = 0.f;
#pragma unroll
    for (int k = 0; k < 16; k++) { e[k] = __expf(wv[k] - m); sum += e[k]; }
    float inv = 1.f / sum;
    float A = 0.f, Bc = 0.f, Cc = 0.f, D = 0.f;
#pragma unroll
    for (int k = 0; k < 16; k++) {
        float p = e[k] * inv;
        A  = fmaf(p, OPC0[k],  A);
        Bc = fmaf(p, OPCA[k],  Bc);
        Cc = fmaf(p, OPCB[k],  Cc);
        D  = fmaf(p, OPCAB[k], D);
    }
    if (i < 9) {
        g_coef[args.s[i].off + rem] = make_float4(A, Bc, Cc, D);
    } else {
        int o = args.s[i].off + rem;
        const int* idx = args.s[i].idx;
        unsigned ia = (unsigned)idx[rem];
        unsigned ib = (unsigned)idx[args.s[i].cnt + rem];
        g_fcidx[o] = ia | (ib << 16);
        g_fch[2 * o]     = __floats2half2_rn(A, Bc);
        g_fch[2 * o + 1] = __floats2half2_rn(Cc, D);
    }
}

// ---------------------------------------------------------------------------
// Conv phase (device): logic-tree conv + 2x2 maxpool, smem in -> smem out.
// Wiring decoded once per block into smem (wire: 9 ints per filter).
// ---------------------------------------------------------------------------
template <int CIN, int HIN, int KS, int PAD, int F, int OFF>
DEV_INLINE void conv_phase(const float* __restrict__ in_s, float* __restrict__ out_s,
                           const int* __restrict__ idx0, const int* __restrict__ idx1,
                           const int* __restrict__ idx2, int* __restrict__ wire,
                           int tid) {
    constexpr int OH  = HIN + 2 * PAD - KS + 1;
    constexpr int OHP = OH / 2;
    constexpr int NOUT = F * OHP * OHP;

    // decode wiring once per block
    for (int f = tid; f < F; f += NT) {
        int sel = 0;
#pragma unroll
        for (int g = 0; g < 2; g++) {
            sel |= (idx1[f * 2 + g] & 3) << (g * 2);
            sel |= (idx1[F * 2 + f * 2 + g] & 3) << (4 + g * 2);
        }
        sel |= (idx2[f] & 1) << 8;
        sel |= (idx2[F + f] & 1) << 9;
        wire[f * 9 + 8] = sel;
#pragma unroll
        for (int j = 0; j < 8; j++) {
            int p = (j < 4) ? idx0[f * 4 + j] : idx0[F * 4 + f * 4 + (j - 4)];
            int c = p / (KS * KS);
            int kk = p % (KS * KS);
            wire[f * 9 + j] = (c << 8) | ((kk / KS) << 4) | (kk % KS);
        }
    }
    __syncthreads();

    for (int out = tid; out < NOUT; out += NT) {
        int px = out % OHP;
        int py = (out / OHP) % OHP;
        int f  = out / (OHP * OHP);

        int pk[8];
#pragma unroll
        for (int j = 0; j < 8; j++) pk[j] = wire[f * 9 + j];
        int sel = wire[f * 9 + 8];

        float4 c0[4], c1[2], c2;
#pragma unroll
        for (int g = 0; g < 4; g++) c0[g] = g_coef[OFF + f * 4 + g];
#pragma unroll
        for (int g = 0; g < 2; g++) c1[g] = g_coef[OFF + F * 4 + f * 2 + g];
        c2 = g_coef[OFF + F * 6 + f];

        float m = -1e30f;
#pragma unroll
        for (int dy = 0; dy < 2; dy++) {
#pragma unroll
            for (int dx = 0; dx < 2; dx++) {
                int y = 2 * py + dy, x = 2 * px + dx;
                float v[8];
#pragma unroll
                for (int j = 0; j < 8; j++) {
                    int iy = y + ((pk[j] >> 4) & 15) - PAD;
                    int ix = x + (pk[j] & 15) - PAD;
                    float t = 0.f;
                    if (PAD == 0 ||
                        ((unsigned)iy < (unsigned)HIN && (unsigned)ix < (unsigned)HIN))
                        t = in_s[(pk[j] >> 8) * HIN * HIN + iy * HIN + ix];
                    v[j] = t;
                }
                float h0[4];
#pragma unroll
                for (int g = 0; g < 4; g++) h0[g] = gate_eval4(c0[g], v[g], v[g + 4]);
                float h1[2];
                h1[0] = gate_eval4(c1[0], sel4(h0, sel & 3), sel4(h0, (sel >> 4) & 3));
                h1[1] = gate_eval4(c1[1], sel4(h0, (sel >> 2) & 3), sel4(h0, (sel >> 6) & 3));
                float ha = ((sel >> 8) & 1) ? h1[1] : h1[0];
                float hb = ((sel >> 9) & 1) ? h1[1] : h1[0];
                float o = gate_eval4(c2, ha, hb);
                m = fmaxf(m, o);
            }
        }
        out_s[out] = m;
    }
    __syncthreads();
}

// ---------------------------------------------------------------------------
// FC phase (device): smem in -> smem out; packed metadata from global.
// ---------------------------------------------------------------------------
template <int DOUT, int GOFF>
DEV_INLINE void fc_phase(const float* __restrict__ in_s, float* __restrict__ out_s,
                         int tid) {
#pragma unroll 2
    for (int o = tid; o < DOUT; o += NT) {
        unsigned pk = __ldg(&g_fcidx[GOFF + o]);
        float a  = in_s[pk & 0xffffu];
        float bb = in_s[pk >> 16];
        __half2 hab = g_fch[2 * (GOFF + o)];
        __half2 hcd = g_fch[2 * (GOFF + o) + 1];
        float2 AB = __half22float2(hab);
        float2 CD = __half22float2(hcd);
        out_s[o] = gate_eval(AB.x, AB.y, CD.x, CD.y, a, bb);
    }
    __syncthreads();
}

// ---------------------------------------------------------------------------
// Kernel 2: mega — whole network per image in shared memory.
// ---------------------------------------------------------------------------
struct ConvIdx {
    const int *c1_0, *c1_1, *c1_2;
    const int *c2_0, *c2_1, *c2_2;
    const int *c3_0, *c3_1, *c3_2;
};

__global__ __launch_bounds__(NT, 1)
void mega_kernel(const float* __restrict__ x, ConvIdx ci, float* __restrict__ out) {
    extern __shared__ float sm[];
    int* wire = reinterpret_cast<int*>(sm + S_WIRE);
    const int tid = threadIdx.x;
    const int b = blockIdx.x;

    // binarize input
    for (int i = tid; i < 784; i += NT)
        sm[S_XBIN + i] = (x[b * 784 + i] > 0.5f) ? 1.f : 0.f;
    __syncthreads();

    conv_phase<1, 28, 5, 0, 16, OFF_C1_0>(sm + S_XBIN, sm + S_ACT1,
                                          ci.c1_0, ci.c1_1, ci.c1_2, wire, tid);
    conv_phase<16, 12, 3, 1, 48, OFF_C2_0>(sm + S_ACT1, sm + S_ACT2,
                                           ci.c2_0, ci.c2_1, ci.c2_2, wire, tid);
    conv_phase<48, 6, 3, 1, 144, OFF_C3_0>(sm + S_ACT2, sm + S_ACT3,
                                           ci.c3_0, ci.c3_1, ci.c3_2, wire, tid);

    fc_phase<20480, FC1_OFF>(sm + S_ACT3, sm + S_FC1, tid);
    fc_phase<10240, FC2_OFF>(sm + S_FC1, sm + S_FC2, tid);
    fc_phase<5120, FC3_OFF>(sm + S_FC2, sm + S_FC1, tid);   // fc3 out reuses fc1 buf

    // groupsum: 10 classes x 512 gates, one warp per class
    const float* f3 = sm + S_FC1;
    int w = tid >> 5, lane = tid & 31;
    if (w < 10) {
        float s = 0.f;
#pragma unroll
        for (int k = 0; k < 16; k++) s += f3[w * 512 + lane + 32 * k];
#pragma unroll
        for (int o = 16; o; o >>= 1) s += __shfl_xor_sync(0xffffffffu, s, o);
        if (lane == 0) out[b * 10 + w] = s * (1.f / 30.f);
    }
}

// ---------------------------------------------------------------------------
static inline int cdiv(int a, int b) { return (a + b - 1) / b; }

extern "C" void kernel_launch(void* const* d_in, const int* in_sizes, int n_in,
                              void* d_out, int out_size) {
    const float* x = (const float*)d_in[0];
    const int B = in_sizes[0] / (28 * 28);

    const int* c1_i0 = (const int*)d_in[1];
    const float* c1_w0 = (const float*)d_in[2];
    const int* c1_i1 = (const int*)d_in[3];
    const float* c1_w1 = (const float*)d_in[4];
    const int* c1_i2 = (const int*)d_in[5];
    const float* c1_w2 = (const float*)d_in[6];
    const int* c2_i0 = (const int*)d_in[7];
    const float* c2_w0 = (const float*)d_in[8];
    const int* c2_i1 = (const int*)d_in[9];
    const float* c2_w1 = (const float*)d_in[10];
    const int* c2_i2 = (const int*)d_in[11];
    const float* c2_w2 = (const float*)d_in[12];
    const int* c3_i0 = (const int*)d_in[13];
    const float* c3_w0 = (const float*)d_in[14];
    const int* c3_i1 = (const int*)d_in[15];
    const float* c3_w1 = (const float*)d_in[16];
    const int* c3_i2 = (const int*)d_in[17];
    const float* c3_w2 = (const float*)d_in[18];
    const int* fc1_i = (const int*)d_in[19];
    const float* fc1_w = (const float*)d_in[20];
    const int* fc2_i = (const int*)d_in[21];
    const float* fc2_w = (const float*)d_in[22];
    const int* fc3_i = (const int*)d_in[23];
    const float* fc3_w = (const float*)d_in[24];
    float* out = (float*)d_out;

    // 1) gate coefficients + fc metadata packing
    CoefArgs ca;
    ca.s[0]  = {c1_w0, nullptr, OFF_C1_0, 64};
    ca.s[1]  = {c1_w1, nullptr, OFF_C1_1, 32};
    ca.s[2]  = {c1_w2, nullptr, OFF_C1_2, 16};
    ca.s[3]  = {c2_w0, nullptr, OFF_C2_0, 192};
    ca.s[4]  = {c2_w1, nullptr, OFF_C2_1, 96};
    ca.s[5]  = {c2_w2, nullptr, OFF_C2_2, 48};
    ca.s[6]  = {c3_w0, nullptr, OFF_C3_0, 576};
    ca.s[7]  = {c3_w1, nullptr, OFF_C3_1, 288};
    ca.s[8]  = {c3_w2, nullptr, OFF_C3_2, 144};
    ca.s[9]  = {fc1_w, fc1_i, FC1_OFF, 20480};
    ca.s[10] = {fc2_w, fc2_i, FC2_OFF, 10240};
    ca.s[11] = {fc3_w, fc3_i, FC3_OFF, 5120};
    coef_kernel<<<cdiv(N_GATES, 256), 256>>>(ca);

    // 2) whole network, one block per image
    ConvIdx ci{c1_i0, c1_i1, c1_i2, c2_i0, c2_i1, c2_i2, c3_i0, c3_i1, c3_i2};
    cudaFuncSetAttribute(mega_kernel, cudaFuncAttributeMaxDynamicSharedMemorySize,
                         SMEM_BYTES);
    mega_kernel<<<B, NT, SMEM_BYTES>>>(x, ci, out);
}